// round 1
// baseline (speedup 1.0000x reference)
#include <cuda_runtime.h>
#include <math.h>

#define SEQ   32768
#define DM    512
#define NCH   256      // number of scan chunks
#define TCH   128      // timesteps per chunk  (NCH*TCH == SEQ)

// ---------------- scratch (device globals; no allocations allowed) ----------
__device__ float g_xr  [(size_t)SEQ * 1024];  // in_proj output (xs | res)
__device__ float g_u   [(size_t)SEQ * DM];    // conv+silu output
__device__ float g_xdbl[(size_t)SEQ * 36];    // x_proj output (delta_r|B|C)
__device__ float g_delta[(size_t)SEQ * DM];   // softplus(dt_proj) output
__device__ float g_dp  [(size_t)SEQ * DM];    // delta_p = delta @ dis_dense
__device__ float g_y   [(size_t)SEQ * DM];    // scan output (pre out_proj)
__device__ float g_P   [NCH * 1024];          // per-chunk prod(a)   [c][d][n]
__device__ float g_S   [NCH * 1024];          // per-chunk local h   [c][d][n]
__device__ float g_H   [NCH * 1024];          // carry-in h per chunk

// ---------------- helpers ----------------------------------------------------
__device__ __forceinline__ float softplusf(float x) {
    float ax = fabsf(x);
    if (ax < 0.25f) {
        // ln(1+e^x) = ln2 + x/2 + x^2/8 - x^4/192 + x^6/2880 ...  (err < 1e-7)
        float x2 = x * x;
        return 0.69314718055994531f + 0.5f * x
             + x2 * (0.125f + x2 * (-1.0f/192.0f + x2 * (1.0f/2880.0f)));
    }
    return fmaxf(x, 0.0f) + log1pf(expf(-ax));
}

__device__ __forceinline__ float siluf(float x) {
    return x / (1.0f + __expf(-x));
}

// ---------------- generic 128x128x8 fp32 tiled GEMM --------------------------
// C[M,N] = A[M,K(lda)] * B      (TRANSB=1: B is [N,K] row-major -> A @ B^T)
//                               (TRANSB=0: B is [K,N] row-major -> A @ B)
// EPI: 0 = none, 1 = finite-filter, 2 = softplus(acc + bias[n])
template <int TRANSB, int EPI>
__global__ __launch_bounds__(256)
void gemm_kernel(const float* __restrict__ A, int lda,
                 const float* __restrict__ B,
                 const float* __restrict__ bias,
                 float* __restrict__ C,
                 int M, int N, int K)
{
    __shared__ float As[8][128];
    __shared__ float Bs[8][128];

    const int tid = threadIdx.x;
    const int m0  = blockIdx.y * 128;
    const int n0  = blockIdx.x * 128;
    const int tr  = tid / 16;        // 0..15 -> rows tr*8..
    const int tc  = tid % 16;        // 0..15 -> cols tc*8..

    float acc[8][8];
    #pragma unroll
    for (int i = 0; i < 8; i++)
        #pragma unroll
        for (int j = 0; j < 8; j++) acc[i][j] = 0.0f;

    for (int k0 = 0; k0 < K; k0 += 8) {
        { // load A tile (128 rows x 8 k), store transposed
            int row = tid >> 1, kq = (tid & 1) * 4;
            float4 v = *reinterpret_cast<const float4*>(
                A + (size_t)(m0 + row) * lda + k0 + kq);
            As[kq+0][row] = v.x; As[kq+1][row] = v.y;
            As[kq+2][row] = v.z; As[kq+3][row] = v.w;
        }
        if (TRANSB) { // B is [N,K]: tile 128 n-rows x 8 k
            int row = tid >> 1, kq = (tid & 1) * 4;
            float4 v = *reinterpret_cast<const float4*>(
                B + (size_t)(n0 + row) * K + k0 + kq);
            Bs[kq+0][row] = v.x; Bs[kq+1][row] = v.y;
            Bs[kq+2][row] = v.z; Bs[kq+3][row] = v.w;
        } else {      // B is [K,N]: tile 8 k-rows x 128 n
            int kk = tid >> 5, nq = (tid & 31) * 4;
            float4 v = *reinterpret_cast<const float4*>(
                B + (size_t)(k0 + kk) * N + n0 + nq);
            *reinterpret_cast<float4*>(&Bs[kk][nq]) = v;
        }
        __syncthreads();

        #pragma unroll
        for (int k = 0; k < 8; k++) {
            float ra[8], rb[8];
            *reinterpret_cast<float4*>(&ra[0]) = *reinterpret_cast<const float4*>(&As[k][tr*8]);
            *reinterpret_cast<float4*>(&ra[4]) = *reinterpret_cast<const float4*>(&As[k][tr*8+4]);
            *reinterpret_cast<float4*>(&rb[0]) = *reinterpret_cast<const float4*>(&Bs[k][tc*8]);
            *reinterpret_cast<float4*>(&rb[4]) = *reinterpret_cast<const float4*>(&Bs[k][tc*8+4]);
            #pragma unroll
            for (int i = 0; i < 8; i++)
                #pragma unroll
                for (int j = 0; j < 8; j++)
                    acc[i][j] = fmaf(ra[i], rb[j], acc[i][j]);
        }
        __syncthreads();
    }

    // epilogue
    #pragma unroll
    for (int i = 0; i < 8; i++) {
        size_t m = (size_t)(m0 + tr * 8 + i);
        float* Cr = C + m * N + n0 + tc * 8;
        float o[8];
        #pragma unroll
        for (int j = 0; j < 8; j++) {
            float v = acc[i][j];
            if (EPI == 1) v = isfinite(v) ? v : 0.0f;
            if (EPI == 2) v = softplusf(v + bias[n0 + tc * 8 + j]);
            o[j] = v;
        }
        *reinterpret_cast<float4*>(Cr)     = make_float4(o[0], o[1], o[2], o[3]);
        *reinterpret_cast<float4*>(Cr + 4) = make_float4(o[4], o[5], o[6], o[7]);
    }
}

// ---------------- depthwise causal conv (width 4) + silu ---------------------
__global__ __launch_bounds__(256)
void conv_silu_kernel(const float* __restrict__ cw, const float* __restrict__ cb)
{
    int idx = blockIdx.x * 256 + threadIdx.x;   // over SEQ*DM
    int t = idx >> 9;
    int d = idx & 511;
    float4 w = reinterpret_cast<const float4*>(cw)[d];   // conv_w[d,0,0..3]
    float acc = cb[d];
    const float* xs = g_xr + d;                 // xs = xr[:, :512]
    acc = fmaf(w.w, xs[(size_t)t * 1024], acc);
    if (t >= 1) acc = fmaf(w.z, xs[(size_t)(t-1) * 1024], acc);
    if (t >= 2) acc = fmaf(w.y, xs[(size_t)(t-2) * 1024], acc);
    if (t >= 3) acc = fmaf(w.x, xs[(size_t)(t-3) * 1024], acc);
    g_u[idx] = siluf(acc);
}

// ---------------- x_proj: xdbl[L,36] = u[L,512] @ x_proj_w[36,512]^T ---------
__global__ __launch_bounds__(288)
void xproj_kernel(const float* __restrict__ w)
{
    __shared__ float Ws[36 * 65];
    __shared__ float Us[8 * 65];
    int tid = threadIdx.x;
    int r0  = blockIdx.x * 8;
    int row = tid / 36;      // 0..7
    int col = tid % 36;      // 0..35
    float acc = 0.0f;

    for (int k0 = 0; k0 < 512; k0 += 64) {
        for (int i = tid; i < 36 * 64; i += 288) {
            int j = i / 64, kk = i % 64;
            Ws[j * 65 + kk] = w[(size_t)j * 512 + k0 + kk];
        }
        for (int i = tid; i < 8 * 64; i += 288) {
            int rr = i / 64, kk = i % 64;
            Us[rr * 65 + kk] = g_u[(size_t)(r0 + rr) * 512 + k0 + kk];
        }
        __syncthreads();
        #pragma unroll
        for (int kk = 0; kk < 64; kk++)
            acc = fmaf(Us[row * 65 + kk], Ws[col * 65 + kk], acc);
        __syncthreads();
    }
    g_xdbl[(size_t)(r0 + row) * 36 + col] = acc;
}

// ---------------- scan pass A: per-chunk products & local scans --------------
__global__ __launch_bounds__(128)
void scanA_kernel(const float* __restrict__ Alog)
{
    int d = blockIdx.x * 128 + threadIdx.x;
    int c = blockIdx.y;
    float A0 = -expf(Alog[d * 2 + 0]);
    float A1 = -expf(Alog[d * 2 + 1]);
    float P0 = 1.f, P1 = 1.f, S0 = 0.f, S1 = 0.f;
    const float* dp = g_dp  + (size_t)c * TCH * DM + d;
    const float* uu = g_u   + (size_t)c * TCH * DM + d;
    const float* xd = g_xdbl + (size_t)c * TCH * 36;
    #pragma unroll 4
    for (int i = 0; i < TCH; i++) {
        float dpv = dp[(size_t)i * DM];
        float uv  = uu[(size_t)i * DM];
        float B0  = xd[i * 36 + 32];
        float B1  = xd[i * 36 + 33];
        float x0 = dpv * A0, x1 = dpv * A1;
        float a0 = 0.f, a1 = 0.f;
        if (fmaxf(x0, x1) > -87.0f) { a0 = __expf(x0); a1 = __expf(x1); }
        S0 = fmaf(a0, S0, dpv * B0 * uv);
        S1 = fmaf(a1, S1, dpv * B1 * uv);
        P0 *= a0; P1 *= a1;
    }
    int dn = d * 2;
    g_P[c * 1024 + dn]     = P0;  g_P[c * 1024 + dn + 1] = P1;
    g_S[c * 1024 + dn]     = S0;  g_S[c * 1024 + dn + 1] = S1;
}

// ---------------- scan pass B: inter-chunk carries ---------------------------
__global__ __launch_bounds__(128)
void scanB_kernel()
{
    int dn = blockIdx.x * 128 + threadIdx.x;   // 0..1023 (grid = 8)
    float h = 0.0f;
    for (int cb = 0; cb < NCH; cb += 16) {
        float p[16], s[16];
        #pragma unroll
        for (int i = 0; i < 16; i++) {
            p[i] = g_P[(cb + i) * 1024 + dn];
            s[i] = g_S[(cb + i) * 1024 + dn];
        }
        #pragma unroll
        for (int i = 0; i < 16; i++) {
            g_H[(cb + i) * 1024 + dn] = h;
            h = fmaf(p[i], h, s[i]);
        }
    }
}

// ---------------- scan pass C: replay with carry + y epilogue ----------------
__global__ __launch_bounds__(128)
void scanC_kernel(const float* __restrict__ Alog, const float* __restrict__ Dw)
{
    int d = blockIdx.x * 128 + threadIdx.x;
    int c = blockIdx.y;
    float A0 = -expf(Alog[d * 2 + 0]);
    float A1 = -expf(Alog[d * 2 + 1]);
    float Dv = Dw[d];
    float h0 = g_H[c * 1024 + d * 2];
    float h1 = g_H[c * 1024 + d * 2 + 1];
    const float* dp  = g_dp   + (size_t)c * TCH * DM + d;
    const float* uu  = g_u    + (size_t)c * TCH * DM + d;
    const float* xd  = g_xdbl + (size_t)c * TCH * 36;
    const float* rs  = g_xr   + (size_t)c * TCH * 1024 + 512 + d;  // res
    float*       yp  = g_y    + (size_t)c * TCH * DM + d;
    #pragma unroll 4
    for (int i = 0; i < TCH; i++) {
        float dpv = dp[(size_t)i * DM];
        float uv  = uu[(size_t)i * DM];
        float B0  = xd[i * 36 + 32];
        float B1  = xd[i * 36 + 33];
        float C0  = xd[i * 36 + 34];
        float C1  = xd[i * 36 + 35];
        float x0 = dpv * A0, x1 = dpv * A1;
        float a0 = 0.f, a1 = 0.f;
        if (fmaxf(x0, x1) > -87.0f) { a0 = __expf(x0); a1 = __expf(x1); }
        h0 = fmaf(a0, h0, dpv * B0 * uv);
        h1 = fmaf(a1, h1, dpv * B1 * uv);
        float y = fmaf(h0, C0, fmaf(h1, C1, uv * Dv));
        y *= siluf(rs[(size_t)i * 1024]);
        yp[(size_t)i * DM] = y;
    }
}

// ---------------- launch -----------------------------------------------------
extern "C" void kernel_launch(void* const* d_in, const int* in_sizes, int n_in,
                              void* d_out, int out_size)
{
    const float* x     = (const float*)d_in[0];
    const float* dis   = (const float*)d_in[1];
    const float* inw   = (const float*)d_in[2];
    const float* convw = (const float*)d_in[3];
    const float* convb = (const float*)d_in[4];
    const float* xpw   = (const float*)d_in[5];
    const float* dtw   = (const float*)d_in[6];
    const float* dtb   = (const float*)d_in[7];
    const float* alog  = (const float*)d_in[8];
    const float* Dw    = (const float*)d_in[9];
    const float* outw  = (const float*)d_in[10];
    float* out = (float*)d_out;

    float *xr, *u_, *xdbl, *delta, *dp, *y;
    cudaGetSymbolAddress((void**)&xr,    g_xr);
    cudaGetSymbolAddress((void**)&u_,    g_u);
    cudaGetSymbolAddress((void**)&xdbl,  g_xdbl);
    cudaGetSymbolAddress((void**)&delta, g_delta);
    cudaGetSymbolAddress((void**)&dp,    g_dp);
    cudaGetSymbolAddress((void**)&y,     g_y);

    // 1) xr = x @ in_proj_w^T    (L x 1024)
    gemm_kernel<1, 0><<<dim3(1024 / 128, SEQ / 128), 256>>>(
        x, 512, inw, nullptr, xr, SEQ, 1024, 512);

    // 2) u = silu(depthwise_conv(xs))
    conv_silu_kernel<<<(SEQ * DM) / 256, 256>>>(convw, convb);

    // 3) xdbl = u @ x_proj_w^T   (L x 36)
    xproj_kernel<<<SEQ / 8, 288>>>(xpw);

    // 4) delta = softplus(xdbl[:, :32] @ dt_proj_w^T + dt_proj_b)  (L x 512)
    gemm_kernel<1, 2><<<dim3(DM / 128, SEQ / 128), 256>>>(
        xdbl, 36, dtw, dtb, delta, SEQ, DM, 32);

    // 5) delta_p = delta @ dis_dense   (adj == dis_dense since d == D_MODEL)
    gemm_kernel<0, 0><<<dim3(DM / 128, SEQ / 128), 256>>>(
        delta, 512, dis, nullptr, dp, SEQ, DM, 512);

    // 6-8) chunked selective scan
    scanA_kernel<<<dim3(4, NCH), 128>>>(alog);
    scanB_kernel<<<8, 128>>>();
    scanC_kernel<<<dim3(4, NCH), 128>>>(alog, Dw);

    // 9) out = y @ out_proj_w^T, zero non-finite
    gemm_kernel<1, 1><<<dim3(DM / 128, SEQ / 128), 256>>>(
        y, 512, outw, nullptr, out, SEQ, DM, 512);
}

// round 3
// speedup vs baseline: 1.6977x; 1.6977x over previous
#include <cuda_runtime.h>
#include <cuda_bf16.h>
#include <math.h>
#include <stdint.h>

#define SEQ   32768
#define DM    512
#define NCH   256
#define TCH   128

// ---------------- scratch (device globals) -----------------------------------
__device__ float g_xr  [(size_t)SEQ * 1024];   // in_proj output (xs | res)
__device__ float g_u   [(size_t)SEQ * DM];     // conv+silu output
__device__ float g_xdbl[(size_t)SEQ * 36];     // x_proj output
__device__ float g_dp  [(size_t)SEQ * DM];     // delta_p
__device__ float g_P   [NCH * 1024];
__device__ float g_S   [NCH * 1024];
__device__ float g_H   [NCH * 1024];

// bf16 split operands for tensor GEMMs
__device__ __nv_bfloat16 g_xh [(size_t)SEQ * DM], g_xl [(size_t)SEQ * DM];
__device__ __nv_bfloat16 g_dh [(size_t)SEQ * DM], g_dl [(size_t)SEQ * DM];
__device__ __nv_bfloat16 g_yh [(size_t)SEQ * DM], g_yl [(size_t)SEQ * DM];
__device__ __nv_bfloat16 g_wih[1024 * 512],       g_wil[1024 * 512];
__device__ __nv_bfloat16 g_dsh[512 * 512],        g_dsl[512 * 512];          // dis^T
__device__ __nv_bfloat16 g_woh[512 * 512],        g_wol[512 * 512];

// ---------------- PTX helpers ---------------------------------------------------
__device__ __forceinline__ uint32_t smem_u32(const void* p) {
    uint32_t a;
    asm("{ .reg .u64 t; cvta.to.shared.u64 t, %1; cvt.u32.u64 %0, t; }" : "=r"(a) : "l"(p));
    return a;
}
#define CP_ASYNC16(dst, src) \
    asm volatile("cp.async.cg.shared.global [%0], [%1], 16;" :: "r"(dst), "l"(src) : "memory")
#define CP_COMMIT() asm volatile("cp.async.commit_group;" ::: "memory")
#define CP_WAIT1()  asm volatile("cp.async.wait_group 1;" ::: "memory")

__device__ __forceinline__ void ldsm4(uint32_t* r, uint32_t addr) {
    asm volatile("ldmatrix.sync.aligned.m8n8.x4.shared.b16 {%0,%1,%2,%3}, [%4];"
                 : "=r"(r[0]), "=r"(r[1]), "=r"(r[2]), "=r"(r[3]) : "r"(addr));
}
__device__ __forceinline__ void mma16816(float* c, const uint32_t* a,
                                         uint32_t b0, uint32_t b1) {
    asm volatile("mma.sync.aligned.m16n8k16.row.col.f32.bf16.bf16.f32 "
                 "{%0,%1,%2,%3}, {%4,%5,%6,%7}, {%8,%9}, {%0,%1,%2,%3};"
                 : "+f"(c[0]), "+f"(c[1]), "+f"(c[2]), "+f"(c[3])
                 : "r"(a[0]), "r"(a[1]), "r"(a[2]), "r"(a[3]), "r"(b0), "r"(b1));
}

// ---------------- math helpers --------------------------------------------------
__device__ __forceinline__ float softplusf(float x) {
    float ax = fabsf(x);
    if (ax < 0.25f) {
        float x2 = x * x;
        return 0.69314718055994531f + 0.5f * x
             + x2 * (0.125f + x2 * (-1.0f/192.0f + x2 * (1.0f/2880.0f)));
    }
    return fmaxf(x, 0.0f) + log1pf(expf(-ax));
}
__device__ __forceinline__ float siluf(float x) { return x / (1.0f + __expf(-x)); }
__device__ __forceinline__ void split_bf16(float v, __nv_bfloat16& h, __nv_bfloat16& l) {
    h = __float2bfloat16(v);
    l = __float2bfloat16(v - __bfloat162float(h));
}

// ---------------- split conversion kernels --------------------------------------
__global__ __launch_bounds__(256)
void cvt_split(const float* __restrict__ s, __nv_bfloat16* __restrict__ hi,
               __nv_bfloat16* __restrict__ lo, int n4)
{
    int i = blockIdx.x * 256 + threadIdx.x;
    if (i >= n4) return;
    float4 v = reinterpret_cast<const float4*>(s)[i];
    __nv_bfloat16 h[4], l[4];
    split_bf16(v.x, h[0], l[0]); split_bf16(v.y, h[1], l[1]);
    split_bf16(v.z, h[2], l[2]); split_bf16(v.w, h[3], l[3]);
    reinterpret_cast<uint2*>(hi)[i] = *reinterpret_cast<uint2*>(h);
    reinterpret_cast<uint2*>(lo)[i] = *reinterpret_cast<uint2*>(l);
}
__global__ __launch_bounds__(256)
void cvt_split_T(const float* __restrict__ s, __nv_bfloat16* __restrict__ hi,
                 __nv_bfloat16* __restrict__ lo)   // 512x512: out[n][k] = s[k][n]
{
    int idx = blockIdx.x * 256 + threadIdx.x;
    int n = idx >> 9, k = idx & 511;
    __nv_bfloat16 h, l;
    split_bf16(s[k * 512 + n], h, l);
    hi[idx] = h; lo[idx] = l;
}

// ---------------- mma.sync split-bf16 GEMM ---------------------------------------
// C[M,N] = (Ah+Al)[M,K] @ (Bh+Bl)[N,K]^T ; fp32 accum.
// CTA tile 128m x 64n, BK=32, 8 warps (4m x 2n), warp tile 32x32.
// SMEM stage: Ah(10240) Al(10240) Bh(5120) Bl(5120) = 30720B, 2 stages.
// EPI: 0 plain store, 1 finite filter
#define PITCH   80
#define STAGE_B 30720
template <int EPI>
__global__ __launch_bounds__(256)
void mma_gemm(const __nv_bfloat16* __restrict__ Ah, const __nv_bfloat16* __restrict__ Al,
              const __nv_bfloat16* __restrict__ Bh, const __nv_bfloat16* __restrict__ Bl,
              float* __restrict__ C, int N, int K)
{
    extern __shared__ char dsm[];
    const uint32_t sb = smem_u32(dsm);
    const int tid = threadIdx.x;
    const int wid = tid >> 5, L = tid & 31;
    const int wm = wid >> 1, wn = wid & 1;     // 4 m-warps x 2 n-warps
    const int m0 = blockIdx.y * 128, n0 = blockIdx.x * 64;

    const __nv_bfloat16* srcA[2] = { Ah + (size_t)m0 * K, Al + (size_t)m0 * K };
    const __nv_bfloat16* srcB[2] = { Bh + (size_t)n0 * K, Bl + (size_t)n0 * K };

    // ldmatrix lane-address components
    const int lrow = (L & 7) + ((L >> 3) & 1) * 8;   // 0..15
    const int lcol = (L >> 4) * 8;                   // 0 or 8 (elements)
    const uint32_t aBase = sb + (wm * 32 + lrow) * PITCH + lcol * 2;
    const uint32_t bBase = sb + 20480 + (wn * 32 + lrow) * PITCH + lcol * 2;

    float acc[2][4][4];
    #pragma unroll
    for (int i = 0; i < 2; i++)
        #pragma unroll
        for (int j = 0; j < 4; j++)
            #pragma unroll
            for (int q = 0; q < 4; q++) acc[i][j][q] = 0.0f;

    const int nk = K / 32;

    // stage loader: 1536 16B-chunks, 6 per thread
    auto load_stage = [&](int ks, int buf) {
        uint32_t dst0 = sb + buf * STAGE_B;
        int k0 = ks * 32;
        #pragma unroll
        for (int it = 0; it < 6; it++) {
            int cid = it * 256 + tid;
            if (cid < 1024) {
                int which = cid >> 9, r = (cid & 511) >> 2, c = cid & 3;
                uint32_t dst = dst0 + which * 10240 + r * PITCH + c * 16;
                const __nv_bfloat16* src = srcA[which] + (size_t)r * K + k0 + c * 8;
                CP_ASYNC16(dst, src);
            } else {
                int c2 = cid - 1024;
                int which = c2 >> 8, r = (c2 & 255) >> 2, c = c2 & 3;
                uint32_t dst = dst0 + 20480 + which * 5120 + r * PITCH + c * 16;
                const __nv_bfloat16* src = srcB[which] + (size_t)r * K + k0 + c * 8;
                CP_ASYNC16(dst, src);
            }
        }
    };

    load_stage(0, 0); CP_COMMIT();
    load_stage(1, 1); CP_COMMIT();

    for (int ks = 0; ks < nk; ks++) {
        CP_WAIT1();
        __syncthreads();
        uint32_t bo = (ks & 1) * STAGE_B;
        #pragma unroll
        for (int kk = 0; kk < 2; kk++) {
            uint32_t a0[4], a1[4], bh0[4], bh1[4], bl0[4], bl1[4];
            uint32_t ko = kk * 32;                 // 16 elems * 2B
            ldsm4(a0,  aBase + bo +         0 * 1280 + ko);
            ldsm4(a1,  aBase + bo +         1 * 1280 + ko);
            ldsm4(bh0, bBase + bo +         0 * 1280 + ko);
            ldsm4(bh1, bBase + bo +         1 * 1280 + ko);
            ldsm4(bl0, bBase + bo + 5120 +  0 * 1280 + ko);
            ldsm4(bl1, bBase + bo + 5120 +  1 * 1280 + ko);
            // Ah*Bh + Ah*Bl
            #pragma unroll
            for (int mi = 0; mi < 2; mi++) {
                uint32_t* a = mi ? a1 : a0;
                mma16816(acc[mi][0], a, bh0[0], bh0[2]);
                mma16816(acc[mi][1], a, bh0[1], bh0[3]);
                mma16816(acc[mi][2], a, bh1[0], bh1[2]);
                mma16816(acc[mi][3], a, bh1[1], bh1[3]);
                mma16816(acc[mi][0], a, bl0[0], bl0[2]);
                mma16816(acc[mi][1], a, bl0[1], bl0[3]);
                mma16816(acc[mi][2], a, bl1[0], bl1[2]);
                mma16816(acc[mi][3], a, bl1[1], bl1[3]);
            }
            // Al*Bh (reuse a regs)
            ldsm4(a0, aBase + bo + 10240 + 0 * 1280 + ko);
            ldsm4(a1, aBase + bo + 10240 + 1 * 1280 + ko);
            #pragma unroll
            for (int mi = 0; mi < 2; mi++) {
                uint32_t* a = mi ? a1 : a0;
                mma16816(acc[mi][0], a, bh0[0], bh0[2]);
                mma16816(acc[mi][1], a, bh0[1], bh0[3]);
                mma16816(acc[mi][2], a, bh1[0], bh1[2]);
                mma16816(acc[mi][3], a, bh1[1], bh1[3]);
            }
        }
        __syncthreads();
        if (ks + 2 < nk) load_stage(ks + 2, ks & 1);
        CP_COMMIT();
    }

    // epilogue: direct register -> global stores
    #pragma unroll
    for (int mi = 0; mi < 2; mi++) {
        #pragma unroll
        for (int j = 0; j < 4; j++) {
            int row = m0 + wm * 32 + mi * 16 + (L >> 2);
            int col = n0 + wn * 32 + j * 8 + (L & 3) * 2;
            float v0 = acc[mi][j][0], v1 = acc[mi][j][1];
            float v2 = acc[mi][j][2], v3 = acc[mi][j][3];
            if (EPI == 1) {
                v0 = isfinite(v0) ? v0 : 0.0f; v1 = isfinite(v1) ? v1 : 0.0f;
                v2 = isfinite(v2) ? v2 : 0.0f; v3 = isfinite(v3) ? v3 : 0.0f;
            }
            *reinterpret_cast<float2*>(C + (size_t)row * N + col)       = make_float2(v0, v1);
            *reinterpret_cast<float2*>(C + (size_t)(row + 8) * N + col) = make_float2(v2, v3);
        }
    }
}

// ---------------- SIMT GEMM (dt_proj: K=32, softplus, bf16-split output) --------
__global__ __launch_bounds__(256)
void dtproj_kernel(const float* __restrict__ A,      // g_xdbl, lda=36
                   const float* __restrict__ B,      // dt_proj_w [512,32]
                   const float* __restrict__ bias,
                   __nv_bfloat16* __restrict__ Chi,
                   __nv_bfloat16* __restrict__ Clo)
{
    __shared__ float As[8][128];
    __shared__ float Bs[8][128];
    const int tid = threadIdx.x;
    const int m0 = blockIdx.y * 128, n0 = blockIdx.x * 128;
    const int tr = tid / 16, tc = tid % 16;
    const int K = 32, N = 512, lda = 36;

    float acc[8][8];
    #pragma unroll
    for (int i = 0; i < 8; i++)
        #pragma unroll
        for (int j = 0; j < 8; j++) acc[i][j] = 0.0f;

    for (int k0 = 0; k0 < K; k0 += 8) {
        {
            int row = tid >> 1, kq = (tid & 1) * 4;
            float4 v = *reinterpret_cast<const float4*>(A + (size_t)(m0 + row) * lda + k0 + kq);
            As[kq+0][row] = v.x; As[kq+1][row] = v.y; As[kq+2][row] = v.z; As[kq+3][row] = v.w;
        }
        {
            int row = tid >> 1, kq = (tid & 1) * 4;
            float4 v = *reinterpret_cast<const float4*>(B + (size_t)(n0 + row) * K + k0 + kq);
            Bs[kq+0][row] = v.x; Bs[kq+1][row] = v.y; Bs[kq+2][row] = v.z; Bs[kq+3][row] = v.w;
        }
        __syncthreads();
        #pragma unroll
        for (int k = 0; k < 8; k++) {
            float ra[8], rb[8];
            *reinterpret_cast<float4*>(&ra[0]) = *reinterpret_cast<const float4*>(&As[k][tr*8]);
            *reinterpret_cast<float4*>(&ra[4]) = *reinterpret_cast<const float4*>(&As[k][tr*8+4]);
            *reinterpret_cast<float4*>(&rb[0]) = *reinterpret_cast<const float4*>(&Bs[k][tc*8]);
            *reinterpret_cast<float4*>(&rb[4]) = *reinterpret_cast<const float4*>(&Bs[k][tc*8+4]);
            #pragma unroll
            for (int i = 0; i < 8; i++)
                #pragma unroll
                for (int j = 0; j < 8; j++)
                    acc[i][j] = fmaf(ra[i], rb[j], acc[i][j]);
        }
        __syncthreads();
    }
    #pragma unroll
    for (int i = 0; i < 8; i++) {
        size_t m = (size_t)(m0 + tr * 8 + i);
        __nv_bfloat16 ho[8], lo[8];
        #pragma unroll
        for (int j = 0; j < 8; j++) {
            float v = softplusf(acc[i][j] + bias[n0 + tc * 8 + j]);
            split_bf16(v, ho[j], lo[j]);
        }
        *reinterpret_cast<uint4*>(Chi + m * N + n0 + tc * 8) = *reinterpret_cast<uint4*>(ho);
        *reinterpret_cast<uint4*>(Clo + m * N + n0 + tc * 8) = *reinterpret_cast<uint4*>(lo);
    }
}

// ---------------- depthwise conv + silu ------------------------------------------
__global__ __launch_bounds__(256)
void conv_silu_kernel(const float* __restrict__ cw, const float* __restrict__ cb)
{
    int idx = blockIdx.x * 256 + threadIdx.x;
    int t = idx >> 9, d = idx & 511;
    float4 w = reinterpret_cast<const float4*>(cw)[d];
    float acc = cb[d];
    const float* xs = g_xr + d;
    acc = fmaf(w.w, xs[(size_t)t * 1024], acc);
    if (t >= 1) acc = fmaf(w.z, xs[(size_t)(t-1) * 1024], acc);
    if (t >= 2) acc = fmaf(w.y, xs[(size_t)(t-2) * 1024], acc);
    if (t >= 3) acc = fmaf(w.x, xs[(size_t)(t-3) * 1024], acc);
    g_u[idx] = siluf(acc);
}

// ---------------- x_proj -----------------------------------------------------------
__global__ __launch_bounds__(288)
void xproj_kernel(const float* __restrict__ w)
{
    __shared__ float Ws[36 * 65];
    __shared__ float Us[8 * 65];
    int tid = threadIdx.x;
    int r0 = blockIdx.x * 8;
    int row = tid / 36, col = tid % 36;
    float acc = 0.0f;
    for (int k0 = 0; k0 < 512; k0 += 64) {
        for (int i = tid; i < 36 * 64; i += 288) {
            int j = i / 64, kk = i % 64;
            Ws[j * 65 + kk] = w[(size_t)j * 512 + k0 + kk];
        }
        for (int i = tid; i < 8 * 64; i += 288) {
            int rr = i / 64, kk = i % 64;
            Us[rr * 65 + kk] = g_u[(size_t)(r0 + rr) * 512 + k0 + kk];
        }
        __syncthreads();
        #pragma unroll
        for (int kk = 0; kk < 64; kk++)
            acc = fmaf(Us[row * 65 + kk], Ws[col * 65 + kk], acc);
        __syncthreads();
    }
    g_xdbl[(size_t)(r0 + row) * 36 + col] = acc;
}

// ---------------- scan passes -------------------------------------------------------
__global__ __launch_bounds__(128)
void scanA_kernel(const float* __restrict__ Alog)
{
    int d = blockIdx.x * 128 + threadIdx.x;
    int c = blockIdx.y;
    float A0 = -expf(Alog[d * 2 + 0]);
    float A1 = -expf(Alog[d * 2 + 1]);
    float P0 = 1.f, P1 = 1.f, S0 = 0.f, S1 = 0.f;
    const float* dp = g_dp + (size_t)c * TCH * DM + d;
    const float* uu = g_u  + (size_t)c * TCH * DM + d;
    const float* xd = g_xdbl + (size_t)c * TCH * 36;
    #pragma unroll 4
    for (int i = 0; i < TCH; i++) {
        float dpv = dp[(size_t)i * DM];
        float uv  = uu[(size_t)i * DM];
        float B0 = xd[i * 36 + 32], B1 = xd[i * 36 + 33];
        float x0 = dpv * A0, x1 = dpv * A1;
        float a0 = 0.f, a1 = 0.f;
        if (fmaxf(x0, x1) > -87.0f) { a0 = __expf(x0); a1 = __expf(x1); }
        S0 = fmaf(a0, S0, dpv * B0 * uv);
        S1 = fmaf(a1, S1, dpv * B1 * uv);
        P0 *= a0; P1 *= a1;
    }
    int dn = d * 2;
    g_P[c * 1024 + dn] = P0; g_P[c * 1024 + dn + 1] = P1;
    g_S[c * 1024 + dn] = S0; g_S[c * 1024 + dn + 1] = S1;
}

__global__ __launch_bounds__(128)
void scanB_kernel()
{
    int dn = blockIdx.x * 128 + threadIdx.x;
    float h = 0.0f;
    for (int cb = 0; cb < NCH; cb += 16) {
        float p[16], s[16];
        #pragma unroll
        for (int i = 0; i < 16; i++) {
            p[i] = g_P[(cb + i) * 1024 + dn];
            s[i] = g_S[(cb + i) * 1024 + dn];
        }
        #pragma unroll
        for (int i = 0; i < 16; i++) {
            g_H[(cb + i) * 1024 + dn] = h;
            h = fmaf(p[i], h, s[i]);
        }
    }
}

__global__ __launch_bounds__(128)
void scanC_kernel(const float* __restrict__ Alog, const float* __restrict__ Dw)
{
    int d = blockIdx.x * 128 + threadIdx.x;
    int c = blockIdx.y;
    float A0 = -expf(Alog[d * 2 + 0]);
    float A1 = -expf(Alog[d * 2 + 1]);
    float Dv = Dw[d];
    float h0 = g_H[c * 1024 + d * 2];
    float h1 = g_H[c * 1024 + d * 2 + 1];
    const float* dp = g_dp + (size_t)c * TCH * DM + d;
    const float* uu = g_u  + (size_t)c * TCH * DM + d;
    const float* xd = g_xdbl + (size_t)c * TCH * 36;
    const float* rs = g_xr + (size_t)c * TCH * 1024 + 512 + d;
    __nv_bfloat16* yh = g_yh + (size_t)c * TCH * DM + d;
    __nv_bfloat16* yl = g_yl + (size_t)c * TCH * DM + d;
    #pragma unroll 4
    for (int i = 0; i < TCH; i++) {
        float dpv = dp[(size_t)i * DM];
        float uv  = uu[(size_t)i * DM];
        float B0 = xd[i * 36 + 32], B1 = xd[i * 36 + 33];
        float C0 = xd[i * 36 + 34], C1 = xd[i * 36 + 35];
        float x0 = dpv * A0, x1 = dpv * A1;
        float a0 = 0.f, a1 = 0.f;
        if (fmaxf(x0, x1) > -87.0f) { a0 = __expf(x0); a1 = __expf(x1); }
        h0 = fmaf(a0, h0, dpv * B0 * uv);
        h1 = fmaf(a1, h1, dpv * B1 * uv);
        float y = fmaf(h0, C0, fmaf(h1, C1, uv * Dv));
        y *= siluf(rs[(size_t)i * 1024]);
        __nv_bfloat16 h, l;
        split_bf16(y, h, l);
        yh[(size_t)i * DM] = h;
        yl[(size_t)i * DM] = l;
    }
}

// ---------------- launch --------------------------------------------------------
extern "C" void kernel_launch(void* const* d_in, const int* in_sizes, int n_in,
                              void* d_out, int out_size)
{
    const float* x     = (const float*)d_in[0];
    const float* dis   = (const float*)d_in[1];
    const float* inw   = (const float*)d_in[2];
    const float* convw = (const float*)d_in[3];
    const float* convb = (const float*)d_in[4];
    const float* xpw   = (const float*)d_in[5];
    const float* dtw   = (const float*)d_in[6];
    const float* dtb   = (const float*)d_in[7];
    const float* alog  = (const float*)d_in[8];
    const float* Dw    = (const float*)d_in[9];
    const float* outw  = (const float*)d_in[10];
    float* out = (float*)d_out;

    float *xr, *dp;
    __nv_bfloat16 *xh, *xl, *dh, *dl, *yh, *yl, *wih, *wil, *dsh, *dsl, *woh, *wol;
    cudaGetSymbolAddress((void**)&xr,  g_xr);
    cudaGetSymbolAddress((void**)&dp,  g_dp);
    cudaGetSymbolAddress((void**)&xh,  g_xh);  cudaGetSymbolAddress((void**)&xl,  g_xl);
    cudaGetSymbolAddress((void**)&dh,  g_dh);  cudaGetSymbolAddress((void**)&dl,  g_dl);
    cudaGetSymbolAddress((void**)&yh,  g_yh);  cudaGetSymbolAddress((void**)&yl,  g_yl);
    cudaGetSymbolAddress((void**)&wih, g_wih); cudaGetSymbolAddress((void**)&wil, g_wil);
    cudaGetSymbolAddress((void**)&dsh, g_dsh); cudaGetSymbolAddress((void**)&dsl, g_dsl);
    cudaGetSymbolAddress((void**)&woh, g_woh); cudaGetSymbolAddress((void**)&wol, g_wol);

    const int GEMM_SMEM = 2 * STAGE_B;   // 61440
    cudaFuncSetAttribute(mma_gemm<0>, cudaFuncAttributeMaxDynamicSharedMemorySize, GEMM_SMEM);
    cudaFuncSetAttribute(mma_gemm<1>, cudaFuncAttributeMaxDynamicSharedMemorySize, GEMM_SMEM);

    // split conversions
    cvt_split<<<(SEQ * DM / 4 + 255) / 256, 256>>>(x, xh, xl, SEQ * DM / 4);
    cvt_split<<<(1024 * 512 / 4 + 255) / 256, 256>>>(inw, wih, wil, 1024 * 512 / 4);
    cvt_split<<<(512 * 512 / 4 + 255) / 256, 256>>>(outw, woh, wol, 512 * 512 / 4);
    cvt_split_T<<<512 * 512 / 256, 256>>>(dis, dsh, dsl);

    // 1) xr = x @ in_proj_w^T   [32768 x 1024]
    mma_gemm<0><<<dim3(1024 / 64, SEQ / 128), 256, GEMM_SMEM>>>(xh, xl, wih, wil, xr, 1024, 512);

    // 2) u = silu(conv(xs))
    conv_silu_kernel<<<(SEQ * DM) / 256, 256>>>(convw, convb);

    // 3) xdbl = u @ x_proj_w^T
    xproj_kernel<<<SEQ / 8, 288>>>(xpw);

    // 4) delta = softplus(xdbl[:, :32] @ dt_proj_w^T + b) -> bf16 split
    dtproj_kernel<<<dim3(DM / 128, SEQ / 128), 256>>>(g_xdbl, dtw, dtb, dh, dl);

    // 5) delta_p = delta @ dis_dense  (dis pre-transposed to [N,K])
    mma_gemm<0><<<dim3(DM / 64, SEQ / 128), 256, GEMM_SMEM>>>(dh, dl, dsh, dsl, dp, DM, 512);

    // 6-8) chunked selective scan
    scanA_kernel<<<dim3(4, NCH), 128>>>(alog);
    scanB_kernel<<<8, 128>>>();
    scanC_kernel<<<dim3(4, NCH), 128>>>(alog, Dw);

    // 9) out = y @ out_proj_w^T, finite filter
    mma_gemm<1><<<dim3(DM / 64, SEQ / 128), 256, GEMM_SMEM>>>(yh, yl, woh, wol, out, DM, 512);
}

// round 4
// speedup vs baseline: 1.7355x; 1.0223x over previous
#include <cuda_runtime.h>
#include <cuda_bf16.h>
#include <math.h>
#include <stdint.h>

#define SEQ   32768
#define DM    512
#define NCH   256
#define TCH   128

// ---------------- scratch (device globals) -----------------------------------
__device__ float g_xr  [(size_t)SEQ * 1024];   // in_proj output (xs | res)
__device__ float g_u   [(size_t)SEQ * DM];     // conv+silu output
__device__ float g_xdbl[(size_t)SEQ * 36];     // x_proj output
__device__ float g_dp  [(size_t)SEQ * DM];     // delta_p
__device__ float g_P   [NCH * 1024];
__device__ float g_S   [NCH * 1024];
__device__ float g_H   [NCH * 1024];

// bf16 split operands for tensor GEMMs
__device__ __nv_bfloat16 g_xh [(size_t)SEQ * DM], g_xl [(size_t)SEQ * DM];
__device__ __nv_bfloat16 g_dh [(size_t)SEQ * DM], g_dl [(size_t)SEQ * DM];
__device__ __nv_bfloat16 g_yh [(size_t)SEQ * DM], g_yl [(size_t)SEQ * DM];
__device__ __nv_bfloat16 g_wih[1024 * 512],       g_wil[1024 * 512];
__device__ __nv_bfloat16 g_dsh[512 * 512],        g_dsl[512 * 512];          // dis^T
__device__ __nv_bfloat16 g_woh[512 * 512],        g_wol[512 * 512];

// ---------------- PTX helpers ---------------------------------------------------
__device__ __forceinline__ uint32_t smem_u32(const void* p) {
    uint32_t a;
    asm("{ .reg .u64 t; cvta.to.shared.u64 t, %1; cvt.u32.u64 %0, t; }" : "=r"(a) : "l"(p));
    return a;
}
#define CP_ASYNC16(dst, src) \
    asm volatile("cp.async.cg.shared.global [%0], [%1], 16;" :: "r"(dst), "l"(src) : "memory")
#define CP_COMMIT() asm volatile("cp.async.commit_group;" ::: "memory")
#define CP_WAIT1()  asm volatile("cp.async.wait_group 1;" ::: "memory")

__device__ __forceinline__ void ldsm4(uint32_t* r, uint32_t addr) {
    asm volatile("ldmatrix.sync.aligned.m8n8.x4.shared.b16 {%0,%1,%2,%3}, [%4];"
                 : "=r"(r[0]), "=r"(r[1]), "=r"(r[2]), "=r"(r[3]) : "r"(addr));
}
__device__ __forceinline__ void mma16816(float* c, const uint32_t* a,
                                         uint32_t b0, uint32_t b1) {
    asm volatile("mma.sync.aligned.m16n8k16.row.col.f32.bf16.bf16.f32 "
                 "{%0,%1,%2,%3}, {%4,%5,%6,%7}, {%8,%9}, {%0,%1,%2,%3};"
                 : "+f"(c[0]), "+f"(c[1]), "+f"(c[2]), "+f"(c[3])
                 : "r"(a[0]), "r"(a[1]), "r"(a[2]), "r"(a[3]), "r"(b0), "r"(b1));
}

// ---------------- math helpers --------------------------------------------------
__device__ __forceinline__ float softplusf(float x) {
    float ax = fabsf(x);
    if (ax < 0.25f) {
        float x2 = x * x;
        return 0.69314718055994531f + 0.5f * x
             + x2 * (0.125f + x2 * (-1.0f/192.0f + x2 * (1.0f/2880.0f)));
    }
    return fmaxf(x, 0.0f) + log1pf(expf(-ax));
}
__device__ __forceinline__ float siluf(float x) { return x / (1.0f + __expf(-x)); }
__device__ __forceinline__ void split_bf16(float v, __nv_bfloat16& h, __nv_bfloat16& l) {
    h = __float2bfloat16(v);
    l = __float2bfloat16(v - __bfloat162float(h));
}

// ---------------- combined split conversion kernel ------------------------------
// segment 0: x      (SEQ*DM/4    float4 -> g_xh/g_xl)        blocks [0, 16384)
// segment 1: inw    (1024*512/4  float4 -> g_wih/g_wil)      blocks [16384, 16896)
// segment 2: outw   (512*512/4   float4 -> g_woh/g_wol)      blocks [16896, 17152)
// segment 3: dis^T  (512*512 scalars   -> g_dsh/g_dsl)       blocks [17152, 18176)
__global__ __launch_bounds__(256)
void cvt_all(const float* __restrict__ x, const float* __restrict__ inw,
             const float* __restrict__ outw, const float* __restrict__ dis)
{
    int b = blockIdx.x;
    if (b < 16384) {
        int i = b * 256 + threadIdx.x;
        float4 v = reinterpret_cast<const float4*>(x)[i];
        __nv_bfloat16 h[4], l[4];
        split_bf16(v.x, h[0], l[0]); split_bf16(v.y, h[1], l[1]);
        split_bf16(v.z, h[2], l[2]); split_bf16(v.w, h[3], l[3]);
        reinterpret_cast<uint2*>(g_xh)[i] = *reinterpret_cast<uint2*>(h);
        reinterpret_cast<uint2*>(g_xl)[i] = *reinterpret_cast<uint2*>(l);
    } else if (b < 16896) {
        int i = (b - 16384) * 256 + threadIdx.x;
        float4 v = reinterpret_cast<const float4*>(inw)[i];
        __nv_bfloat16 h[4], l[4];
        split_bf16(v.x, h[0], l[0]); split_bf16(v.y, h[1], l[1]);
        split_bf16(v.z, h[2], l[2]); split_bf16(v.w, h[3], l[3]);
        reinterpret_cast<uint2*>(g_wih)[i] = *reinterpret_cast<uint2*>(h);
        reinterpret_cast<uint2*>(g_wil)[i] = *reinterpret_cast<uint2*>(l);
    } else if (b < 17152) {
        int i = (b - 16896) * 256 + threadIdx.x;
        float4 v = reinterpret_cast<const float4*>(outw)[i];
        __nv_bfloat16 h[4], l[4];
        split_bf16(v.x, h[0], l[0]); split_bf16(v.y, h[1], l[1]);
        split_bf16(v.z, h[2], l[2]); split_bf16(v.w, h[3], l[3]);
        reinterpret_cast<uint2*>(g_woh)[i] = *reinterpret_cast<uint2*>(h);
        reinterpret_cast<uint2*>(g_wol)[i] = *reinterpret_cast<uint2*>(l);
    } else {
        int idx = (b - 17152) * 256 + threadIdx.x;   // out[n][k] = dis[k][n]
        int n = idx >> 9, k = idx & 511;
        __nv_bfloat16 h, l;
        split_bf16(dis[k * 512 + n], h, l);
        g_dsh[idx] = h; g_dsl[idx] = l;
    }
}

// ---------------- mma.sync split-bf16 GEMM ---------------------------------------
// C[M,N] = (Ah+Al)[M,K] @ (Bh+Bl)[N,K]^T ; fp32 accum.
// CTA tile 128m x 128n, BK=32, 8 warps (4m x 2n), warp tile 32x64.
// SMEM stage: Ah Al Bh Bl, each 128 rows x 80B pitch = 10240B -> 40960B, 2 stages.
// EPI: 0 plain store, 1 finite filter
#define PITCH   80
#define STAGE_B 40960
template <int EPI>
__global__ __launch_bounds__(256, 2)
void mma_gemm(const __nv_bfloat16* __restrict__ Ah, const __nv_bfloat16* __restrict__ Al,
              const __nv_bfloat16* __restrict__ Bh, const __nv_bfloat16* __restrict__ Bl,
              float* __restrict__ C, int N, int K)
{
    extern __shared__ char dsm[];
    const uint32_t sb = smem_u32(dsm);
    const int tid = threadIdx.x;
    const int wid = tid >> 5, L = tid & 31;
    const int wm = wid >> 1, wn = wid & 1;     // 4 m-warps x 2 n-warps
    const int m0 = blockIdx.y * 128, n0 = blockIdx.x * 128;

    const __nv_bfloat16* srcs[4] = {
        Ah + (size_t)m0 * K, Al + (size_t)m0 * K,
        Bh + (size_t)n0 * K, Bl + (size_t)n0 * K };

    // ldmatrix lane addressing: lane -> row (L&15), col-half (L>>4)*16B
    const int lrow = L & 15;
    const int lcolB = (L >> 4) * 16;
    const uint32_t aBase = sb + (wm * 32 + lrow) * PITCH + lcolB;           // Ah @ 0
    const uint32_t bBase = sb + 20480 + (wn * 64 + lrow) * PITCH + lcolB;   // Bh @ 20480

    float acc[2][8][4];
    #pragma unroll
    for (int i = 0; i < 2; i++)
        #pragma unroll
        for (int j = 0; j < 8; j++)
            #pragma unroll
            for (int q = 0; q < 4; q++) acc[i][j][q] = 0.0f;

    const int nk = K / 32;

    // stage loader: 2048 16B-chunks, 8 per thread
    auto load_stage = [&](int ks, int buf) {
        uint32_t dst0 = sb + buf * STAGE_B;
        int k0 = ks * 32;
        #pragma unroll
        for (int it = 0; it < 8; it++) {
            int cid = it * 256 + tid;
            int mat = cid >> 9, w = cid & 511;
            int r = w >> 2, c = w & 3;
            uint32_t dst = dst0 + mat * 10240 + r * PITCH + c * 16;
            const __nv_bfloat16* src = srcs[mat] + (size_t)r * K + k0 + c * 8;
            CP_ASYNC16(dst, src);
        }
    };

    load_stage(0, 0); CP_COMMIT();
    load_stage(1, 1); CP_COMMIT();

    for (int ks = 0; ks < nk; ks++) {
        CP_WAIT1();
        __syncthreads();
        uint32_t bo = (ks & 1) * STAGE_B;
        #pragma unroll
        for (int kk = 0; kk < 2; kk++) {
            uint32_t ko = kk * 32;                 // 16 k-elems * 2B
            uint32_t ah[2][4], al[2][4], b[4][4];
            #pragma unroll
            for (int mi = 0; mi < 2; mi++) {
                ldsm4(ah[mi], aBase + bo +         mi * 1280 + ko);
                ldsm4(al[mi], aBase + bo + 10240 + mi * 1280 + ko);
            }
            // Bh: 4 ldsm over n=64
            #pragma unroll
            for (int t = 0; t < 4; t++)
                ldsm4(b[t], bBase + bo + t * 1280 + ko);
            #pragma unroll
            for (int mi = 0; mi < 2; mi++)
                #pragma unroll
                for (int t = 0; t < 4; t++) {
                    mma16816(acc[mi][2*t+0], ah[mi], b[t][0], b[t][2]);
                    mma16816(acc[mi][2*t+1], ah[mi], b[t][1], b[t][3]);
                    mma16816(acc[mi][2*t+0], al[mi], b[t][0], b[t][2]);
                    mma16816(acc[mi][2*t+1], al[mi], b[t][1], b[t][3]);
                }
            // Bl: reuse b regs
            #pragma unroll
            for (int t = 0; t < 4; t++)
                ldsm4(b[t], bBase + bo + 10240 + t * 1280 + ko);
            #pragma unroll
            for (int mi = 0; mi < 2; mi++)
                #pragma unroll
                for (int t = 0; t < 4; t++) {
                    mma16816(acc[mi][2*t+0], ah[mi], b[t][0], b[t][2]);
                    mma16816(acc[mi][2*t+1], ah[mi], b[t][1], b[t][3]);
                }
        }
        __syncthreads();
        if (ks + 2 < nk) load_stage(ks + 2, ks & 1);
        CP_COMMIT();
    }

    // epilogue: direct register -> global stores
    #pragma unroll
    for (int mi = 0; mi < 2; mi++) {
        #pragma unroll
        for (int j = 0; j < 8; j++) {
            int row = m0 + wm * 32 + mi * 16 + (L >> 2);
            int col = n0 + wn * 64 + j * 8 + (L & 3) * 2;
            float v0 = acc[mi][j][0], v1 = acc[mi][j][1];
            float v2 = acc[mi][j][2], v3 = acc[mi][j][3];
            if (EPI == 1) {
                v0 = isfinite(v0) ? v0 : 0.0f; v1 = isfinite(v1) ? v1 : 0.0f;
                v2 = isfinite(v2) ? v2 : 0.0f; v3 = isfinite(v3) ? v3 : 0.0f;
            }
            *reinterpret_cast<float2*>(C + (size_t)row * N + col)       = make_float2(v0, v1);
            *reinterpret_cast<float2*>(C + (size_t)(row + 8) * N + col) = make_float2(v2, v3);
        }
    }
}

// ---------------- SIMT GEMM (dt_proj: K=32, softplus, bf16-split output) --------
__global__ __launch_bounds__(256)
void dtproj_kernel(const float* __restrict__ A,      // g_xdbl, lda=36
                   const float* __restrict__ B,      // dt_proj_w [512,32]
                   const float* __restrict__ bias,
                   __nv_bfloat16* __restrict__ Chi,
                   __nv_bfloat16* __restrict__ Clo)
{
    __shared__ float As[8][128];
    __shared__ float Bs[8][128];
    const int tid = threadIdx.x;
    const int m0 = blockIdx.y * 128, n0 = blockIdx.x * 128;
    const int tr = tid / 16, tc = tid % 16;
    const int K = 32, N = 512, lda = 36;

    float acc[8][8];
    #pragma unroll
    for (int i = 0; i < 8; i++)
        #pragma unroll
        for (int j = 0; j < 8; j++) acc[i][j] = 0.0f;

    for (int k0 = 0; k0 < K; k0 += 8) {
        {
            int row = tid >> 1, kq = (tid & 1) * 4;
            float4 v = *reinterpret_cast<const float4*>(A + (size_t)(m0 + row) * lda + k0 + kq);
            As[kq+0][row] = v.x; As[kq+1][row] = v.y; As[kq+2][row] = v.z; As[kq+3][row] = v.w;
        }
        {
            int row = tid >> 1, kq = (tid & 1) * 4;
            float4 v = *reinterpret_cast<const float4*>(B + (size_t)(n0 + row) * K + k0 + kq);
            Bs[kq+0][row] = v.x; Bs[kq+1][row] = v.y; Bs[kq+2][row] = v.z; Bs[kq+3][row] = v.w;
        }
        __syncthreads();
        #pragma unroll
        for (int k = 0; k < 8; k++) {
            float ra[8], rb[8];
            *reinterpret_cast<float4*>(&ra[0]) = *reinterpret_cast<const float4*>(&As[k][tr*8]);
            *reinterpret_cast<float4*>(&ra[4]) = *reinterpret_cast<const float4*>(&As[k][tr*8+4]);
            *reinterpret_cast<float4*>(&rb[0]) = *reinterpret_cast<const float4*>(&Bs[k][tc*8]);
            *reinterpret_cast<float4*>(&rb[4]) = *reinterpret_cast<const float4*>(&Bs[k][tc*8+4]);
            #pragma unroll
            for (int i = 0; i < 8; i++)
                #pragma unroll
                for (int j = 0; j < 8; j++)
                    acc[i][j] = fmaf(ra[i], rb[j], acc[i][j]);
        }
        __syncthreads();
    }
    #pragma unroll
    for (int i = 0; i < 8; i++) {
        size_t m = (size_t)(m0 + tr * 8 + i);
        __nv_bfloat16 ho[8], lo[8];
        #pragma unroll
        for (int j = 0; j < 8; j++) {
            float v = softplusf(acc[i][j] + bias[n0 + tc * 8 + j]);
            split_bf16(v, ho[j], lo[j]);
        }
        *reinterpret_cast<uint4*>(Chi + m * N + n0 + tc * 8) = *reinterpret_cast<uint4*>(ho);
        *reinterpret_cast<uint4*>(Clo + m * N + n0 + tc * 8) = *reinterpret_cast<uint4*>(lo);
    }
}

// ---------------- depthwise conv + silu ------------------------------------------
__global__ __launch_bounds__(256)
void conv_silu_kernel(const float* __restrict__ cw, const float* __restrict__ cb)
{
    int idx = blockIdx.x * 256 + threadIdx.x;
    int t = idx >> 9, d = idx & 511;
    float4 w = reinterpret_cast<const float4*>(cw)[d];
    float acc = cb[d];
    const float* xs = g_xr + d;
    acc = fmaf(w.w, xs[(size_t)t * 1024], acc);
    if (t >= 1) acc = fmaf(w.z, xs[(size_t)(t-1) * 1024], acc);
    if (t >= 2) acc = fmaf(w.y, xs[(size_t)(t-2) * 1024], acc);
    if (t >= 3) acc = fmaf(w.x, xs[(size_t)(t-3) * 1024], acc);
    g_u[idx] = siluf(acc);
}

// ---------------- x_proj -----------------------------------------------------------
__global__ __launch_bounds__(288)
void xproj_kernel(const float* __restrict__ w)
{
    __shared__ float Ws[36 * 65];
    __shared__ float Us[8 * 65];
    int tid = threadIdx.x;
    int r0 = blockIdx.x * 8;
    int row = tid / 36, col = tid % 36;
    float acc = 0.0f;
    for (int k0 = 0; k0 < 512; k0 += 64) {
        for (int i = tid; i < 36 * 64; i += 288) {
            int j = i / 64, kk = i % 64;
            Ws[j * 65 + kk] = w[(size_t)j * 512 + k0 + kk];
        }
        for (int i = tid; i < 8 * 64; i += 288) {
            int rr = i / 64, kk = i % 64;
            Us[rr * 65 + kk] = g_u[(size_t)(r0 + rr) * 512 + k0 + kk];
        }
        __syncthreads();
        #pragma unroll
        for (int kk = 0; kk < 64; kk++)
            acc = fmaf(Us[row * 65 + kk], Ws[col * 65 + kk], acc);
        __syncthreads();
    }
    g_xdbl[(size_t)(r0 + row) * 36 + col] = acc;
}

// ---------------- scan passes -------------------------------------------------------
__global__ __launch_bounds__(128)
void scanA_kernel(const float* __restrict__ Alog)
{
    int d = blockIdx.x * 128 + threadIdx.x;
    int c = blockIdx.y;
    float A0 = -expf(Alog[d * 2 + 0]);
    float A1 = -expf(Alog[d * 2 + 1]);
    float P0 = 1.f, P1 = 1.f, S0 = 0.f, S1 = 0.f;
    const float* dp = g_dp + (size_t)c * TCH * DM + d;
    const float* uu = g_u  + (size_t)c * TCH * DM + d;
    const float* xd = g_xdbl + (size_t)c * TCH * 36;
    #pragma unroll 4
    for (int i = 0; i < TCH; i++) {
        float dpv = dp[(size_t)i * DM];
        float uv  = uu[(size_t)i * DM];
        float B0 = xd[i * 36 + 32], B1 = xd[i * 36 + 33];
        float x0 = dpv * A0, x1 = dpv * A1;
        float a0 = 0.f, a1 = 0.f;
        if (fmaxf(x0, x1) > -87.0f) { a0 = __expf(x0); a1 = __expf(x1); }
        S0 = fmaf(a0, S0, dpv * B0 * uv);
        S1 = fmaf(a1, S1, dpv * B1 * uv);
        P0 *= a0; P1 *= a1;
    }
    int dn = d * 2;
    g_P[c * 1024 + dn] = P0; g_P[c * 1024 + dn + 1] = P1;
    g_S[c * 1024 + dn] = S0; g_S[c * 1024 + dn + 1] = S1;
}

__global__ __launch_bounds__(128)
void scanB_kernel()
{
    int dn = blockIdx.x * 128 + threadIdx.x;
    float h = 0.0f;
    for (int cb = 0; cb < NCH; cb += 16) {
        float p[16], s[16];
        #pragma unroll
        for (int i = 0; i < 16; i++) {
            p[i] = g_P[(cb + i) * 1024 + dn];
            s[i] = g_S[(cb + i) * 1024 + dn];
        }
        #pragma unroll
        for (int i = 0; i < 16; i++) {
            g_H[(cb + i) * 1024 + dn] = h;
            h = fmaf(p[i], h, s[i]);
        }
    }
}

__global__ __launch_bounds__(128)
void scanC_kernel(const float* __restrict__ Alog, const float* __restrict__ Dw)
{
    int d = blockIdx.x * 128 + threadIdx.x;
    int c = blockIdx.y;
    float A0 = -expf(Alog[d * 2 + 0]);
    float A1 = -expf(Alog[d * 2 + 1]);
    float Dv = Dw[d];
    float h0 = g_H[c * 1024 + d * 2];
    float h1 = g_H[c * 1024 + d * 2 + 1];
    const float* dp = g_dp + (size_t)c * TCH * DM + d;
    const float* uu = g_u  + (size_t)c * TCH * DM + d;
    const float* xd = g_xdbl + (size_t)c * TCH * 36;
    const float* rs = g_xr + (size_t)c * TCH * 1024 + 512 + d;
    __nv_bfloat16* yh = g_yh + (size_t)c * TCH * DM + d;
    __nv_bfloat16* yl = g_yl + (size_t)c * TCH * DM + d;
    #pragma unroll 4
    for (int i = 0; i < TCH; i++) {
        float dpv = dp[(size_t)i * DM];
        float uv  = uu[(size_t)i * DM];
        float B0 = xd[i * 36 + 32], B1 = xd[i * 36 + 33];
        float C0 = xd[i * 36 + 34], C1 = xd[i * 36 + 35];
        float x0 = dpv * A0, x1 = dpv * A1;
        float a0 = 0.f, a1 = 0.f;
        if (fmaxf(x0, x1) > -87.0f) { a0 = __expf(x0); a1 = __expf(x1); }
        h0 = fmaf(a0, h0, dpv * B0 * uv);
        h1 = fmaf(a1, h1, dpv * B1 * uv);
        float y = fmaf(h0, C0, fmaf(h1, C1, uv * Dv));
        y *= siluf(rs[(size_t)i * 1024]);
        __nv_bfloat16 h, l;
        split_bf16(y, h, l);
        yh[(size_t)i * DM] = h;
        yl[(size_t)i * DM] = l;
    }
}

// ---------------- launch --------------------------------------------------------
extern "C" void kernel_launch(void* const* d_in, const int* in_sizes, int n_in,
                              void* d_out, int out_size)
{
    const float* x     = (const float*)d_in[0];
    const float* dis   = (const float*)d_in[1];
    const float* inw   = (const float*)d_in[2];
    const float* convw = (const float*)d_in[3];
    const float* convb = (const float*)d_in[4];
    const float* xpw   = (const float*)d_in[5];
    const float* dtw   = (const float*)d_in[6];
    const float* dtb   = (const float*)d_in[7];
    const float* alog  = (const float*)d_in[8];
    const float* Dw    = (const float*)d_in[9];
    const float* outw  = (const float*)d_in[10];
    float* out = (float*)d_out;

    float *xr, *dp;
    __nv_bfloat16 *xh, *xl, *dh, *dl, *yh, *yl, *wih, *wil, *dsh, *dsl, *woh, *wol;
    cudaGetSymbolAddress((void**)&xr,  g_xr);
    cudaGetSymbolAddress((void**)&dp,  g_dp);
    cudaGetSymbolAddress((void**)&xh,  g_xh);  cudaGetSymbolAddress((void**)&xl,  g_xl);
    cudaGetSymbolAddress((void**)&dh,  g_dh);  cudaGetSymbolAddress((void**)&dl,  g_dl);
    cudaGetSymbolAddress((void**)&yh,  g_yh);  cudaGetSymbolAddress((void**)&yl,  g_yl);
    cudaGetSymbolAddress((void**)&wih, g_wih); cudaGetSymbolAddress((void**)&wil, g_wil);
    cudaGetSymbolAddress((void**)&dsh, g_dsh); cudaGetSymbolAddress((void**)&dsl, g_dsl);
    cudaGetSymbolAddress((void**)&woh, g_woh); cudaGetSymbolAddress((void**)&wol, g_wol);

    const int GEMM_SMEM = 2 * STAGE_B;   // 81920
    cudaFuncSetAttribute(mma_gemm<0>, cudaFuncAttributeMaxDynamicSharedMemorySize, GEMM_SMEM);
    cudaFuncSetAttribute(mma_gemm<1>, cudaFuncAttributeMaxDynamicSharedMemorySize, GEMM_SMEM);

    // 0) all split conversions in one launch
    cvt_all<<<18176, 256>>>(x, inw, outw, dis);

    // 1) xr = x @ in_proj_w^T   [32768 x 1024]
    mma_gemm<0><<<dim3(1024 / 128, SEQ / 128), 256, GEMM_SMEM>>>(xh, xl, wih, wil, xr, 1024, 512);

    // 2) u = silu(conv(xs))
    conv_silu_kernel<<<(SEQ * DM) / 256, 256>>>(convw, convb);

    // 3) xdbl = u @ x_proj_w^T
    xproj_kernel<<<SEQ / 8, 288>>>(xpw);

    // 4) delta = softplus(xdbl[:, :32] @ dt_proj_w^T + b) -> bf16 split
    dtproj_kernel<<<dim3(DM / 128, SEQ / 128), 256>>>(g_xdbl, dtw, dtb, dh, dl);

    // 5) delta_p = delta @ dis_dense  (dis pre-transposed to [N,K])
    mma_gemm<0><<<dim3(DM / 128, SEQ / 128), 256, GEMM_SMEM>>>(dh, dl, dsh, dsl, dp, DM, 512);

    // 6-8) chunked selective scan
    scanA_kernel<<<dim3(4, NCH), 128>>>(alog);
    scanB_kernel<<<8, 128>>>();
    scanC_kernel<<<dim3(4, NCH), 128>>>(alog, Dw);

    // 9) out = y @ out_proj_w^T, finite filter
    mma_gemm<1><<<dim3(DM / 128, SEQ / 128), 256, GEMM_SMEM>>>(yh, yl, woh, wol, out, DM, 512);
}

// round 5
// speedup vs baseline: 1.9744x; 1.1377x over previous
#include <cuda_runtime.h>
#include <cuda_bf16.h>
#include <math.h>
#include <stdint.h>

#define SEQ   32768
#define DM    512
#define NCH   256
#define TCH   128

// ---------------- scratch (device globals) -----------------------------------
__device__ float g_xr  [(size_t)SEQ * 1024];   // in_proj output (xs | res)
__device__ float g_u   [(size_t)SEQ * DM];     // conv+silu output
__device__ float g_xdbl[(size_t)SEQ * 36];     // x_proj output
__device__ float g_dp  [(size_t)SEQ * DM];     // delta_p
__device__ float g_P   [NCH * 1024];
__device__ float g_S   [NCH * 1024];
__device__ float g_H   [NCH * 1024];

// bf16 split operands for tensor GEMMs
__device__ __nv_bfloat16 g_xh [(size_t)SEQ * DM], g_xl [(size_t)SEQ * DM];
__device__ __nv_bfloat16 g_uh [(size_t)SEQ * DM], g_ul [(size_t)SEQ * DM];
__device__ __nv_bfloat16 g_dh [(size_t)SEQ * DM], g_dl [(size_t)SEQ * DM];
__device__ __nv_bfloat16 g_yh [(size_t)SEQ * DM], g_yl [(size_t)SEQ * DM];
__device__ __nv_bfloat16 g_wih[1024 * 512],       g_wil[1024 * 512];
__device__ __nv_bfloat16 g_dsh[512 * 512],        g_dsl[512 * 512];          // dis^T
__device__ __nv_bfloat16 g_woh[512 * 512],        g_wol[512 * 512];
__device__ __nv_bfloat16 g_xph[128 * 512],        g_xpl[128 * 512];          // x_proj_w padded

// ---------------- PTX helpers ---------------------------------------------------
__device__ __forceinline__ uint32_t smem_u32(const void* p) {
    uint32_t a;
    asm("{ .reg .u64 t; cvta.to.shared.u64 t, %1; cvt.u32.u64 %0, t; }" : "=r"(a) : "l"(p));
    return a;
}
#define CP_ASYNC16(dst, src) \
    asm volatile("cp.async.cg.shared.global [%0], [%1], 16;" :: "r"(dst), "l"(src) : "memory")
#define CP_COMMIT() asm volatile("cp.async.commit_group;" ::: "memory")
#define CP_WAIT1()  asm volatile("cp.async.wait_group 1;" ::: "memory")

__device__ __forceinline__ void ldsm4(uint32_t* r, uint32_t addr) {
    asm volatile("ldmatrix.sync.aligned.m8n8.x4.shared.b16 {%0,%1,%2,%3}, [%4];"
                 : "=r"(r[0]), "=r"(r[1]), "=r"(r[2]), "=r"(r[3]) : "r"(addr));
}
__device__ __forceinline__ void mma16816(float* c, const uint32_t* a,
                                         uint32_t b0, uint32_t b1) {
    asm volatile("mma.sync.aligned.m16n8k16.row.col.f32.bf16.bf16.f32 "
                 "{%0,%1,%2,%3}, {%4,%5,%6,%7}, {%8,%9}, {%0,%1,%2,%3};"
                 : "+f"(c[0]), "+f"(c[1]), "+f"(c[2]), "+f"(c[3])
                 : "r"(a[0]), "r"(a[1]), "r"(a[2]), "r"(a[3]), "r"(b0), "r"(b1));
}

// ---------------- math helpers --------------------------------------------------
__device__ __forceinline__ float softplusf(float x) {
    float ax = fabsf(x);
    if (ax < 0.25f) {
        float x2 = x * x;
        return 0.69314718055994531f + 0.5f * x
             + x2 * (0.125f + x2 * (-1.0f/192.0f + x2 * (1.0f/2880.0f)));
    }
    return fmaxf(x, 0.0f) + log1pf(expf(-ax));
}
__device__ __forceinline__ float siluf(float x) { return x / (1.0f + __expf(-x)); }
__device__ __forceinline__ void split_bf16(float v, __nv_bfloat16& h, __nv_bfloat16& l) {
    h = __float2bfloat16(v);
    l = __float2bfloat16(v - __bfloat162float(h));
}

// ---------------- combined split conversion kernel ------------------------------
// seg 0: x      16384 blocks   seg 1: inw 512   seg 2: outw 256
// seg 3: dis^T  1024           seg 4: xpw padded to [128,512], 256 blocks
__global__ __launch_bounds__(256)
void cvt_all(const float* __restrict__ x, const float* __restrict__ inw,
             const float* __restrict__ outw, const float* __restrict__ dis,
             const float* __restrict__ xpw)
{
    int b = blockIdx.x;
    if (b < 16384) {
        int i = b * 256 + threadIdx.x;
        float4 v = reinterpret_cast<const float4*>(x)[i];
        __nv_bfloat16 h[4], l[4];
        split_bf16(v.x, h[0], l[0]); split_bf16(v.y, h[1], l[1]);
        split_bf16(v.z, h[2], l[2]); split_bf16(v.w, h[3], l[3]);
        reinterpret_cast<uint2*>(g_xh)[i] = *reinterpret_cast<uint2*>(h);
        reinterpret_cast<uint2*>(g_xl)[i] = *reinterpret_cast<uint2*>(l);
    } else if (b < 16896) {
        int i = (b - 16384) * 256 + threadIdx.x;
        float4 v = reinterpret_cast<const float4*>(inw)[i];
        __nv_bfloat16 h[4], l[4];
        split_bf16(v.x, h[0], l[0]); split_bf16(v.y, h[1], l[1]);
        split_bf16(v.z, h[2], l[2]); split_bf16(v.w, h[3], l[3]);
        reinterpret_cast<uint2*>(g_wih)[i] = *reinterpret_cast<uint2*>(h);
        reinterpret_cast<uint2*>(g_wil)[i] = *reinterpret_cast<uint2*>(l);
    } else if (b < 17152) {
        int i = (b - 16896) * 256 + threadIdx.x;
        float4 v = reinterpret_cast<const float4*>(outw)[i];
        __nv_bfloat16 h[4], l[4];
        split_bf16(v.x, h[0], l[0]); split_bf16(v.y, h[1], l[1]);
        split_bf16(v.z, h[2], l[2]); split_bf16(v.w, h[3], l[3]);
        reinterpret_cast<uint2*>(g_woh)[i] = *reinterpret_cast<uint2*>(h);
        reinterpret_cast<uint2*>(g_wol)[i] = *reinterpret_cast<uint2*>(l);
    } else if (b < 18176) {
        int idx = (b - 17152) * 256 + threadIdx.x;   // out[n][k] = dis[k][n]
        int n = idx >> 9, k = idx & 511;
        __nv_bfloat16 h, l;
        split_bf16(dis[k * 512 + n], h, l);
        g_dsh[idx] = h; g_dsl[idx] = l;
    } else {
        int idx = (b - 18176) * 256 + threadIdx.x;   // 128x512 padded
        int r = idx >> 9;
        __nv_bfloat16 h = __float2bfloat16(0.0f), l = h;
        if (r < 36) split_bf16(xpw[idx], h, l);
        g_xph[idx] = h; g_xpl[idx] = l;
    }
}

// ---------------- mma.sync split-bf16 GEMM ---------------------------------------
// C[M,N] = (Ah+Al)[M,K] @ (Bh+Bl)[N,K]^T ; fp32 accum.
// CTA tile 128m x 128n, BK=32, 8 warps (4m x 2n), warp tile 32x64.
// EPI: 0 plain store, 1 finite filter, 2 narrow store (cols < ldc only)
#define PITCH   80
#define STAGE_B 40960
template <int EPI>
__global__ __launch_bounds__(256, 2)
void mma_gemm(const __nv_bfloat16* __restrict__ Ah, const __nv_bfloat16* __restrict__ Al,
              const __nv_bfloat16* __restrict__ Bh, const __nv_bfloat16* __restrict__ Bl,
              float* __restrict__ C, int N, int K, int ldc)
{
    extern __shared__ char dsm[];
    const uint32_t sb = smem_u32(dsm);
    const int tid = threadIdx.x;
    const int wid = tid >> 5, L = tid & 31;
    const int wm = wid >> 1, wn = wid & 1;
    const int m0 = blockIdx.y * 128, n0 = blockIdx.x * 128;

    const __nv_bfloat16* srcs[4] = {
        Ah + (size_t)m0 * K, Al + (size_t)m0 * K,
        Bh + (size_t)n0 * K, Bl + (size_t)n0 * K };

    const int lrow = L & 15;
    const int lcolB = (L >> 4) * 16;
    const uint32_t aBase = sb + (wm * 32 + lrow) * PITCH + lcolB;
    const uint32_t bBase = sb + 20480 + (wn * 64 + lrow) * PITCH + lcolB;

    float acc[2][8][4];
    #pragma unroll
    for (int i = 0; i < 2; i++)
        #pragma unroll
        for (int j = 0; j < 8; j++)
            #pragma unroll
            for (int q = 0; q < 4; q++) acc[i][j][q] = 0.0f;

    const int nk = K / 32;

    auto load_stage = [&](int ks, int buf) {
        uint32_t dst0 = sb + buf * STAGE_B;
        int k0 = ks * 32;
        #pragma unroll
        for (int it = 0; it < 8; it++) {
            int cid = it * 256 + tid;
            int mat = cid >> 9, w = cid & 511;
            int r = w >> 2, c = w & 3;
            uint32_t dst = dst0 + mat * 10240 + r * PITCH + c * 16;
            const __nv_bfloat16* src = srcs[mat] + (size_t)r * K + k0 + c * 8;
            CP_ASYNC16(dst, src);
        }
    };

    load_stage(0, 0); CP_COMMIT();
    load_stage(1, 1); CP_COMMIT();

    for (int ks = 0; ks < nk; ks++) {
        CP_WAIT1();
        __syncthreads();
        uint32_t bo = (ks & 1) * STAGE_B;
        #pragma unroll
        for (int kk = 0; kk < 2; kk++) {
            uint32_t ko = kk * 32;
            uint32_t ah[2][4], al[2][4], b[4][4];
            #pragma unroll
            for (int mi = 0; mi < 2; mi++) {
                ldsm4(ah[mi], aBase + bo +         mi * 1280 + ko);
                ldsm4(al[mi], aBase + bo + 10240 + mi * 1280 + ko);
            }
            #pragma unroll
            for (int t = 0; t < 4; t++)
                ldsm4(b[t], bBase + bo + t * 1280 + ko);
            #pragma unroll
            for (int mi = 0; mi < 2; mi++)
                #pragma unroll
                for (int t = 0; t < 4; t++) {
                    mma16816(acc[mi][2*t+0], ah[mi], b[t][0], b[t][2]);
                    mma16816(acc[mi][2*t+1], ah[mi], b[t][1], b[t][3]);
                    mma16816(acc[mi][2*t+0], al[mi], b[t][0], b[t][2]);
                    mma16816(acc[mi][2*t+1], al[mi], b[t][1], b[t][3]);
                }
            #pragma unroll
            for (int t = 0; t < 4; t++)
                ldsm4(b[t], bBase + bo + 10240 + t * 1280 + ko);
            #pragma unroll
            for (int mi = 0; mi < 2; mi++)
                #pragma unroll
                for (int t = 0; t < 4; t++) {
                    mma16816(acc[mi][2*t+0], ah[mi], b[t][0], b[t][2]);
                    mma16816(acc[mi][2*t+1], ah[mi], b[t][1], b[t][3]);
                }
        }
        __syncthreads();
        if (ks + 2 < nk) load_stage(ks + 2, ks & 1);
        CP_COMMIT();
    }

    // epilogue
    #pragma unroll
    for (int mi = 0; mi < 2; mi++) {
        #pragma unroll
        for (int j = 0; j < 8; j++) {
            int row = m0 + wm * 32 + mi * 16 + (L >> 2);
            int col = n0 + wn * 64 + j * 8 + (L & 3) * 2;
            float v0 = acc[mi][j][0], v1 = acc[mi][j][1];
            float v2 = acc[mi][j][2], v3 = acc[mi][j][3];
            if (EPI == 1) {
                v0 = isfinite(v0) ? v0 : 0.0f; v1 = isfinite(v1) ? v1 : 0.0f;
                v2 = isfinite(v2) ? v2 : 0.0f; v3 = isfinite(v3) ? v3 : 0.0f;
            }
            if (EPI == 2) {
                if (col + 1 < ldc) {
                    *reinterpret_cast<float2*>(C + (size_t)row * ldc + col)       = make_float2(v0, v1);
                    *reinterpret_cast<float2*>(C + (size_t)(row + 8) * ldc + col) = make_float2(v2, v3);
                }
            } else {
                *reinterpret_cast<float2*>(C + (size_t)row * ldc + col)       = make_float2(v0, v1);
                *reinterpret_cast<float2*>(C + (size_t)(row + 8) * ldc + col) = make_float2(v2, v3);
            }
        }
    }
}

// ---------------- SIMT GEMM (dt_proj: K=32, softplus, bf16-split output) --------
__global__ __launch_bounds__(256)
void dtproj_kernel(const float* __restrict__ A,      // g_xdbl, lda=36
                   const float* __restrict__ B,      // dt_proj_w [512,32]
                   const float* __restrict__ bias,
                   __nv_bfloat16* __restrict__ Chi,
                   __nv_bfloat16* __restrict__ Clo)
{
    __shared__ float As[8][128];
    __shared__ float Bs[8][128];
    const int tid = threadIdx.x;
    const int m0 = blockIdx.y * 128, n0 = blockIdx.x * 128;
    const int tr = tid / 16, tc = tid % 16;
    const int K = 32, N = 512, lda = 36;

    float acc[8][8];
    #pragma unroll
    for (int i = 0; i < 8; i++)
        #pragma unroll
        for (int j = 0; j < 8; j++) acc[i][j] = 0.0f;

    for (int k0 = 0; k0 < K; k0 += 8) {
        {
            int row = tid >> 1, kq = (tid & 1) * 4;
            float4 v = *reinterpret_cast<const float4*>(A + (size_t)(m0 + row) * lda + k0 + kq);
            As[kq+0][row] = v.x; As[kq+1][row] = v.y; As[kq+2][row] = v.z; As[kq+3][row] = v.w;
        }
        {
            int row = tid >> 1, kq = (tid & 1) * 4;
            float4 v = *reinterpret_cast<const float4*>(B + (size_t)(n0 + row) * K + k0 + kq);
            Bs[kq+0][row] = v.x; Bs[kq+1][row] = v.y; Bs[kq+2][row] = v.z; Bs[kq+3][row] = v.w;
        }
        __syncthreads();
        #pragma unroll
        for (int k = 0; k < 8; k++) {
            float ra[8], rb[8];
            *reinterpret_cast<float4*>(&ra[0]) = *reinterpret_cast<const float4*>(&As[k][tr*8]);
            *reinterpret_cast<float4*>(&ra[4]) = *reinterpret_cast<const float4*>(&As[k][tr*8+4]);
            *reinterpret_cast<float4*>(&rb[0]) = *reinterpret_cast<const float4*>(&Bs[k][tc*8]);
            *reinterpret_cast<float4*>(&rb[4]) = *reinterpret_cast<const float4*>(&Bs[k][tc*8+4]);
            #pragma unroll
            for (int i = 0; i < 8; i++)
                #pragma unroll
                for (int j = 0; j < 8; j++)
                    acc[i][j] = fmaf(ra[i], rb[j], acc[i][j]);
        }
        __syncthreads();
    }
    #pragma unroll
    for (int i = 0; i < 8; i++) {
        size_t m = (size_t)(m0 + tr * 8 + i);
        __nv_bfloat16 ho[8], lo[8];
        #pragma unroll
        for (int j = 0; j < 8; j++) {
            float v = softplusf(acc[i][j] + bias[n0 + tc * 8 + j]);
            split_bf16(v, ho[j], lo[j]);
        }
        *reinterpret_cast<uint4*>(Chi + m * N + n0 + tc * 8) = *reinterpret_cast<uint4*>(ho);
        *reinterpret_cast<uint4*>(Clo + m * N + n0 + tc * 8) = *reinterpret_cast<uint4*>(lo);
    }
}

// ---------------- depthwise conv + silu (+ bf16 split of u) ----------------------
__global__ __launch_bounds__(256)
void conv_silu_kernel(const float* __restrict__ cw, const float* __restrict__ cb)
{
    int idx = blockIdx.x * 256 + threadIdx.x;
    int t = idx >> 9, d = idx & 511;
    float4 w = reinterpret_cast<const float4*>(cw)[d];
    float acc = cb[d];
    const float* xs = g_xr + d;
    acc = fmaf(w.w, xs[(size_t)t * 1024], acc);
    if (t >= 1) acc = fmaf(w.z, xs[(size_t)(t-1) * 1024], acc);
    if (t >= 2) acc = fmaf(w.y, xs[(size_t)(t-2) * 1024], acc);
    if (t >= 3) acc = fmaf(w.x, xs[(size_t)(t-3) * 1024], acc);
    float u = siluf(acc);
    g_u[idx] = u;
    __nv_bfloat16 h, l;
    split_bf16(u, h, l);
    g_uh[idx] = h;
    g_ul[idx] = l;
}

// ---------------- scan passes -------------------------------------------------------
__global__ __launch_bounds__(128)
void scanA_kernel(const float* __restrict__ Alog)
{
    int d = blockIdx.x * 128 + threadIdx.x;
    int c = blockIdx.y;
    float A0 = -expf(Alog[d * 2 + 0]);
    float A1 = -expf(Alog[d * 2 + 1]);
    float P0 = 1.f, P1 = 1.f, S0 = 0.f, S1 = 0.f;
    const float* dp = g_dp + (size_t)c * TCH * DM + d;
    const float* uu = g_u  + (size_t)c * TCH * DM + d;
    const float* xd = g_xdbl + (size_t)c * TCH * 36;
    #pragma unroll 4
    for (int i = 0; i < TCH; i++) {
        float dpv = dp[(size_t)i * DM];
        float uv  = uu[(size_t)i * DM];
        float B0 = xd[i * 36 + 32], B1 = xd[i * 36 + 33];
        float x0 = dpv * A0, x1 = dpv * A1;
        float a0 = 0.f, a1 = 0.f;
        if (fmaxf(x0, x1) > -87.0f) { a0 = __expf(x0); a1 = __expf(x1); }
        S0 = fmaf(a0, S0, dpv * B0 * uv);
        S1 = fmaf(a1, S1, dpv * B1 * uv);
        P0 *= a0; P1 *= a1;
    }
    int dn = d * 2;
    g_P[c * 1024 + dn] = P0; g_P[c * 1024 + dn + 1] = P1;
    g_S[c * 1024 + dn] = S0; g_S[c * 1024 + dn + 1] = S1;
}

__global__ __launch_bounds__(128)
void scanB_kernel()
{
    int dn = blockIdx.x * 128 + threadIdx.x;
    float h = 0.0f;
    for (int cb = 0; cb < NCH; cb += 16) {
        float p[16], s[16];
        #pragma unroll
        for (int i = 0; i < 16; i++) {
            p[i] = g_P[(cb + i) * 1024 + dn];
            s[i] = g_S[(cb + i) * 1024 + dn];
        }
        #pragma unroll
        for (int i = 0; i < 16; i++) {
            g_H[(cb + i) * 1024 + dn] = h;
            h = fmaf(p[i], h, s[i]);
        }
    }
}

__global__ __launch_bounds__(128)
void scanC_kernel(const float* __restrict__ Alog, const float* __restrict__ Dw)
{
    int d = blockIdx.x * 128 + threadIdx.x;
    int c = blockIdx.y;
    float A0 = -expf(Alog[d * 2 + 0]);
    float A1 = -expf(Alog[d * 2 + 1]);
    float Dv = Dw[d];
    float h0 = g_H[c * 1024 + d * 2];
    float h1 = g_H[c * 1024 + d * 2 + 1];
    const float* dp = g_dp + (size_t)c * TCH * DM + d;
    const float* uu = g_u  + (size_t)c * TCH * DM + d;
    const float* xd = g_xdbl + (size_t)c * TCH * 36;
    const float* rs = g_xr + (size_t)c * TCH * 1024 + 512 + d;
    __nv_bfloat16* yh = g_yh + (size_t)c * TCH * DM + d;
    __nv_bfloat16* yl = g_yl + (size_t)c * TCH * DM + d;
    #pragma unroll 4
    for (int i = 0; i < TCH; i++) {
        float dpv = dp[(size_t)i * DM];
        float uv  = uu[(size_t)i * DM];
        float B0 = xd[i * 36 + 32], B1 = xd[i * 36 + 33];
        float C0 = xd[i * 36 + 34], C1 = xd[i * 36 + 35];
        float x0 = dpv * A0, x1 = dpv * A1;
        float a0 = 0.f, a1 = 0.f;
        if (fmaxf(x0, x1) > -87.0f) { a0 = __expf(x0); a1 = __expf(x1); }
        h0 = fmaf(a0, h0, dpv * B0 * uv);
        h1 = fmaf(a1, h1, dpv * B1 * uv);
        float y = fmaf(h0, C0, fmaf(h1, C1, uv * Dv));
        y *= siluf(rs[(size_t)i * 1024]);
        __nv_bfloat16 h, l;
        split_bf16(y, h, l);
        yh[(size_t)i * DM] = h;
        yl[(size_t)i * DM] = l;
    }
}

// ---------------- launch --------------------------------------------------------
extern "C" void kernel_launch(void* const* d_in, const int* in_sizes, int n_in,
                              void* d_out, int out_size)
{
    const float* x     = (const float*)d_in[0];
    const float* dis   = (const float*)d_in[1];
    const float* inw   = (const float*)d_in[2];
    const float* convw = (const float*)d_in[3];
    const float* convb = (const float*)d_in[4];
    const float* xpw   = (const float*)d_in[5];
    const float* dtw   = (const float*)d_in[6];
    const float* dtb   = (const float*)d_in[7];
    const float* alog  = (const float*)d_in[8];
    const float* Dw    = (const float*)d_in[9];
    const float* outw  = (const float*)d_in[10];
    float* out = (float*)d_out;

    float *xr, *dp, *xdbl;
    __nv_bfloat16 *xh, *xl, *uh, *ul, *dh, *dl, *yh, *yl;
    __nv_bfloat16 *wih, *wil, *dsh, *dsl, *woh, *wol, *xph, *xpl;
    cudaGetSymbolAddress((void**)&xr,   g_xr);
    cudaGetSymbolAddress((void**)&dp,   g_dp);
    cudaGetSymbolAddress((void**)&xdbl, g_xdbl);
    cudaGetSymbolAddress((void**)&xh,  g_xh);  cudaGetSymbolAddress((void**)&xl,  g_xl);
    cudaGetSymbolAddress((void**)&uh,  g_uh);  cudaGetSymbolAddress((void**)&ul,  g_ul);
    cudaGetSymbolAddress((void**)&dh,  g_dh);  cudaGetSymbolAddress((void**)&dl,  g_dl);
    cudaGetSymbolAddress((void**)&yh,  g_yh);  cudaGetSymbolAddress((void**)&yl,  g_yl);
    cudaGetSymbolAddress((void**)&wih, g_wih); cudaGetSymbolAddress((void**)&wil, g_wil);
    cudaGetSymbolAddress((void**)&dsh, g_dsh); cudaGetSymbolAddress((void**)&dsl, g_dsl);
    cudaGetSymbolAddress((void**)&woh, g_woh); cudaGetSymbolAddress((void**)&wol, g_wol);
    cudaGetSymbolAddress((void**)&xph, g_xph); cudaGetSymbolAddress((void**)&xpl, g_xpl);

    const int GEMM_SMEM = 2 * STAGE_B;   // 81920
    cudaFuncSetAttribute(mma_gemm<0>, cudaFuncAttributeMaxDynamicSharedMemorySize, GEMM_SMEM);
    cudaFuncSetAttribute(mma_gemm<1>, cudaFuncAttributeMaxDynamicSharedMemorySize, GEMM_SMEM);
    cudaFuncSetAttribute(mma_gemm<2>, cudaFuncAttributeMaxDynamicSharedMemorySize, GEMM_SMEM);

    // 0) all split conversions (x, in_proj_w, out_proj_w, dis^T, x_proj_w padded)
    cvt_all<<<18432, 256>>>(x, inw, outw, dis, xpw);

    // 1) xr = x @ in_proj_w^T   [32768 x 1024]
    mma_gemm<0><<<dim3(8, SEQ / 128), 256, GEMM_SMEM>>>(xh, xl, wih, wil, xr, 1024, 512, 1024);

    // 2) u = silu(conv(xs))  (+ bf16 split)
    conv_silu_kernel<<<(SEQ * DM) / 256, 256>>>(convw, convb);

    // 3) xdbl = u @ x_proj_w^T  (tensor core, N padded to 128, store cols<36)
    mma_gemm<2><<<dim3(1, SEQ / 128), 256, GEMM_SMEM>>>(uh, ul, xph, xpl, xdbl, 128, 512, 36);

    // 4) delta = softplus(xdbl[:, :32] @ dt_proj_w^T + b) -> bf16 split
    dtproj_kernel<<<dim3(DM / 128, SEQ / 128), 256>>>(g_xdbl, dtw, dtb, dh, dl);

    // 5) delta_p = delta @ dis_dense  (dis pre-transposed to [N,K])
    mma_gemm<0><<<dim3(DM / 128, SEQ / 128), 256, GEMM_SMEM>>>(dh, dl, dsh, dsl, dp, DM, 512, DM);

    // 6-8) chunked selective scan
    scanA_kernel<<<dim3(4, NCH), 128>>>(alog);
    scanB_kernel<<<8, 128>>>();
    scanC_kernel<<<dim3(4, NCH), 128>>>(alog, Dw);

    // 9) out = y @ out_proj_w^T, finite filter
    mma_gemm<1><<<dim3(DM / 128, SEQ / 128), 256, GEMM_SMEM>>>(yh, yl, woh, wol, out, DM, 512, DM);
}